// round 6
// baseline (speedup 1.0000x reference)
#include <cuda_runtime.h>
#include <cstdint>

#define DSZ 64
#define N_SRC 50000
#define N_ALL 100000
#define E_ALL 1600000
#define TPB 256
#define ETILE 64
#define PSTR 66      // >= ETILE, even -> 8B-aligned pairs; mod 32 = 2 skews banks
#define GRID 296

typedef unsigned long long f32x2_t;

__device__ __align__(16) float g_y1[(size_t)N_ALL * DSZ];

__device__ __forceinline__ f32x2_t ffma2(f32x2_t a, f32x2_t b, f32x2_t c) {
    f32x2_t d;
    asm("fma.rn.f32x2 %0, %1, %2, %3;" : "=l"(d) : "l"(a), "l"(b), "l"(c));
    return d;
}
__device__ __forceinline__ f32x2_t dup2(float x) {
    f32x2_t d; unsigned u = __float_as_uint(x);
    asm("mov.b64 %0, {%1, %1};" : "=l"(d) : "r"(u));
    return d;
}
__device__ __forceinline__ void unpack2(f32x2_t v, float& lo, float& hi) {
    unsigned a, b;
    asm("mov.b64 {%0, %1}, %2;" : "=r"(a), "=r"(b) : "l"(v));
    lo = __uint_as_float(a); hi = __uint_as_float(b);
}
__device__ __forceinline__ const float* node_ptr(const float* __restrict__ se,
                                                 const float* __restrict__ de,
                                                 int v) {
    return (v < N_SRC) ? se + (size_t)v * DSZ : de + (size_t)(v - N_SRC) * DSZ;
}

// ================= node transform: y1 = X @ W1^T + (b1+b2) =================
__global__ __launch_bounds__(TPB, 2)
void node_transform_kernel(const float* __restrict__ src_emb,
                           const float* __restrict__ dst_emb,
                           const float* __restrict__ W1,
                           const float* __restrict__ b1,
                           const float* __restrict__ b2) {
    __shared__ __align__(16) float WT[DSZ * DSZ];   // WT[d*64+o]
    __shared__ __align__(16) float xt[DSZ * PSTR];  // xt[d*PSTR+e], e in [0,64)

    const int tid = threadIdx.x;
    for (int i = tid; i < DSZ * DSZ; i += TPB) {
        int o = i >> 6, d = i & 63;
        WT[d * DSZ + o] = W1[i];
    }
    const int lane = tid & 31, w = tid >> 5;
    const int q16 = lane & 15, eg = lane >> 4;
    const int e_base = (w * 2 + eg) * 4;   // 16 groups x 4 nodes, max 60..63
    const int eA = tid & 63;               // phase-A node slot
    const int jg = tid >> 6;               // 0..3 quad group

    float4 bias;
    bias.x = b1[4 * q16 + 0] + b2[4 * q16 + 0];
    bias.y = b1[4 * q16 + 1] + b2[4 * q16 + 1];
    bias.z = b1[4 * q16 + 2] + b2[4 * q16 + 2];
    bias.w = b1[4 * q16 + 3] + b2[4 * q16 + 3];

    const int ntiles = (N_ALL + ETILE - 1) / ETILE;   // 1563
    float4 xa[4];
    int tile = blockIdx.x;
    if (tile < ntiles) {
        int v = tile * ETILE + eA; if (v >= N_ALL) v = 0;
        const float* ps = node_ptr(src_emb, dst_emb, v);
        #pragma unroll
        for (int j = 0; j < 4; j++) xa[j] = ((const float4*)ps)[jg * 4 + j];
    }
    for (; tile < ntiles; tile += gridDim.x) {
        const int base = tile * ETILE;
        #pragma unroll
        for (int j = 0; j < 4; j++) {
            int r = 4 * (jg * 4 + j);
            xt[(r + 0) * PSTR + eA] = xa[j].x;
            xt[(r + 1) * PSTR + eA] = xa[j].y;
            xt[(r + 2) * PSTR + eA] = xa[j].z;
            xt[(r + 3) * PSTR + eA] = xa[j].w;
        }
        __syncthreads();
        int nt = tile + gridDim.x;
        if (nt < ntiles) {
            int v = nt * ETILE + eA; if (v >= N_ALL) v = 0;
            const float* ps = node_ptr(src_emb, dst_emb, v);
            #pragma unroll
            for (int j = 0; j < 4; j++) xa[j] = ((const float4*)ps)[jg * 4 + j];
        }
        f32x2_t a00 = 0, a01 = 0, a10 = 0, a11 = 0,
                a20 = 0, a21 = 0, a30 = 0, a31 = 0;
        #pragma unroll 8
        for (int d = 0; d < DSZ; d++) {
            float4 wv = *(const float4*)&WT[d * DSZ + 4 * q16];
            f32x2_t p01 = *(const f32x2_t*)&xt[d * PSTR + e_base];
            f32x2_t p23 = *(const f32x2_t*)&xt[d * PSTR + e_base + 2];
            f32x2_t wx = dup2(wv.x), wy = dup2(wv.y), wz = dup2(wv.z), ww = dup2(wv.w);
            a00 = ffma2(p01, wx, a00); a01 = ffma2(p23, wx, a01);
            a10 = ffma2(p01, wy, a10); a11 = ffma2(p23, wy, a11);
            a20 = ffma2(p01, wz, a20); a21 = ffma2(p23, wz, a21);
            a30 = ffma2(p01, ww, a30); a31 = ffma2(p23, ww, a31);
        }
        float v0[4], v1[4], v2[4], v3[4];
        unpack2(a00, v0[0], v0[1]); unpack2(a01, v0[2], v0[3]);
        unpack2(a10, v1[0], v1[1]); unpack2(a11, v1[2], v1[3]);
        unpack2(a20, v2[0], v2[1]); unpack2(a21, v2[2], v2[3]);
        unpack2(a30, v3[0], v3[1]); unpack2(a31, v3[2], v3[3]);
        #pragma unroll
        for (int k = 0; k < 4; k++) {
            int n = base + e_base + k;
            if (n < N_ALL) {
                float4 r;
                r.x = v0[k] + bias.x; r.y = v1[k] + bias.y;
                r.z = v2[k] + bias.z; r.w = v3[k] + bias.w;
                *(float4*)&g_y1[(size_t)n * DSZ + 4 * q16] = r;
            }
        }
        __syncthreads();
    }
}

// ============ edge kernel: scatter norm*(y1[src] + W2 (xs*xd)) ============
__global__ __launch_bounds__(TPB, 2)
void edge_kernel(const float* __restrict__ src_emb,
                 const float* __restrict__ dst_emb,
                 const float* __restrict__ norm,
                 const float* __restrict__ W2,
                 const int* __restrict__ esrc,
                 const int* __restrict__ edst,
                 float* __restrict__ out) {
    __shared__ __align__(16) float WT[DSZ * DSZ];
    __shared__ __align__(16) float pt[DSZ * PSTR];

    const int tid = threadIdx.x;
    for (int i = tid; i < DSZ * DSZ; i += TPB) {
        int o = i >> 6, d = i & 63;
        WT[d * DSZ + o] = W2[i];
    }
    const int lane = tid & 31, w = tid >> 5;
    const int q16 = lane & 15, eg = lane >> 4;
    const int e_base = (w * 2 + eg) * 4;
    const int eA = tid & 63;
    const int jg = tid >> 6;

    const int ntiles = E_ALL / ETILE;   // 25000 exact
    float4 xa[4], xb[4];
    int tile = blockIdx.x;
    if (tile < ntiles) {
        int ei = tile * ETILE + eA;
        const float* ps = node_ptr(src_emb, dst_emb, esrc[ei]);
        const float* pd = node_ptr(src_emb, dst_emb, edst[ei]);
        #pragma unroll
        for (int j = 0; j < 4; j++) {
            xa[j] = ((const float4*)ps)[jg * 4 + j];
            xb[j] = ((const float4*)pd)[jg * 4 + j];
        }
    }
    for (; tile < ntiles; tile += gridDim.x) {
        const int ebase = tile * ETILE;
        #pragma unroll
        for (int j = 0; j < 4; j++) {
            int r = 4 * (jg * 4 + j);
            pt[(r + 0) * PSTR + eA] = xa[j].x * xb[j].x;
            pt[(r + 1) * PSTR + eA] = xa[j].y * xb[j].y;
            pt[(r + 2) * PSTR + eA] = xa[j].z * xb[j].z;
            pt[(r + 3) * PSTR + eA] = xa[j].w * xb[j].w;
        }
        __syncthreads();
        int nt = tile + gridDim.x;
        if (nt < ntiles) {                     // prefetch next tile (overlaps phase B)
            int ei = nt * ETILE + eA;
            const float* ps = node_ptr(src_emb, dst_emb, esrc[ei]);
            const float* pd = node_ptr(src_emb, dst_emb, edst[ei]);
            #pragma unroll
            for (int j = 0; j < 4; j++) {
                xa[j] = ((const float4*)ps)[jg * 4 + j];
                xb[j] = ((const float4*)pd)[jg * 4 + j];
            }
        }
        f32x2_t a00 = 0, a01 = 0, a10 = 0, a11 = 0,
                a20 = 0, a21 = 0, a30 = 0, a31 = 0;
        #pragma unroll 8
        for (int d = 0; d < DSZ; d++) {
            float4 wv = *(const float4*)&WT[d * DSZ + 4 * q16];
            f32x2_t p01 = *(const f32x2_t*)&pt[d * PSTR + e_base];
            f32x2_t p23 = *(const f32x2_t*)&pt[d * PSTR + e_base + 2];
            f32x2_t wx = dup2(wv.x), wy = dup2(wv.y), wz = dup2(wv.z), ww = dup2(wv.w);
            a00 = ffma2(p01, wx, a00); a01 = ffma2(p23, wx, a01);
            a10 = ffma2(p01, wy, a10); a11 = ffma2(p23, wy, a11);
            a20 = ffma2(p01, wz, a20); a21 = ffma2(p23, wz, a21);
            a30 = ffma2(p01, ww, a30); a31 = ffma2(p23, ww, a31);
        }
        float v0[4], v1[4], v2[4], v3[4];
        unpack2(a00, v0[0], v0[1]); unpack2(a01, v0[2], v0[3]);
        unpack2(a10, v1[0], v1[1]); unpack2(a11, v1[2], v1[3]);
        unpack2(a20, v2[0], v2[1]); unpack2(a21, v2[2], v2[3]);
        unpack2(a30, v3[0], v3[1]); unpack2(a31, v3[2], v3[3]);
        #pragma unroll
        for (int k = 0; k < 4; k++) {
            const int ei = ebase + e_base + k;
            const int s  = esrc[ei];
            const float nv = norm[ei];
            float4 y = *(const float4*)&g_y1[(size_t)s * DSZ + 4 * q16];
            float mx = nv * (v0[k] + y.x);
            float my = nv * (v1[k] + y.y);
            float mz = nv * (v2[k] + y.z);
            float mw = nv * (v3[k] + y.w);
            uintptr_t addr = (uintptr_t)&out[(size_t)edst[ei] * DSZ + 4 * q16];
            asm volatile("red.global.add.v4.f32 [%0], {%1, %2, %3, %4};"
                         :: "l"(addr), "f"(mx), "f"(my), "f"(mz), "f"(mw)
                         : "memory");
        }
        __syncthreads();
    }
}

// ================= epilogue: LeakyReLU(0.2) in place =================
__global__ void lrelu_kernel(float* __restrict__ out, int n4) {
    int i = blockIdx.x * blockDim.x + threadIdx.x;
    if (i < n4) {
        float4 v = ((float4*)out)[i];
        v.x = v.x > 0.f ? v.x : 0.2f * v.x;
        v.y = v.y > 0.f ? v.y : 0.2f * v.y;
        v.z = v.z > 0.f ? v.z : 0.2f * v.z;
        v.w = v.w > 0.f ? v.w : 0.2f * v.w;
        ((float4*)out)[i] = v;
    }
}

extern "C" void kernel_launch(void* const* d_in, const int* in_sizes, int n_in,
                              void* d_out, int out_size) {
    const float* src_emb = (const float*)d_in[0];
    const float* dst_emb = (const float*)d_in[1];
    const float* norm    = (const float*)d_in[2];
    const float* W1      = (const float*)d_in[3];
    const float* b1      = (const float*)d_in[4];
    const float* W2      = (const float*)d_in[5];
    const float* b2      = (const float*)d_in[6];
    const int*   esrc    = (const int*)d_in[7];
    const int*   edst    = (const int*)d_in[8];
    float* out = (float*)d_out;

    cudaMemsetAsync(d_out, 0, (size_t)out_size * sizeof(float));

    node_transform_kernel<<<GRID, TPB>>>(src_emb, dst_emb, W1, b1, b2);
    edge_kernel<<<GRID, TPB>>>(src_emb, dst_emb, norm, W2, esrc, edst, out);

    int n4 = out_size / 4;
    lrelu_kernel<<<(n4 + 255) / 256, 256>>>(out, n4);
}